// round 13
// baseline (speedup 1.0000x reference)
#include <cuda_runtime.h>
#include <cuda_bf16.h>
#include <math.h>
#include <stdint.h>

#define Bb 2
#define Ss 2048
#define Dd 1024
#define Hh 16
#define DKk 64
#define GPAD 72   // bf16 columns per SMEM row (144 B stride, ldmatrix conflict-free)

// Scratch (device globals: allocation-free rule). All pre-split bf16 hi/lo.
#define QKV_ELEMS ((size_t)Bb * Hh * Ss * DKk)
__device__ __nv_bfloat16 g_qh[QKV_ELEMS], g_ql[QKV_ELEMS];
__device__ __nv_bfloat16 g_kh[QKV_ELEMS], g_kl[QKV_ELEMS];
__device__ __nv_bfloat16 g_vh[QKV_ELEMS], g_vl[QKV_ELEMS];
__device__ __nv_bfloat16 g_ath[(size_t)Bb * Ss * Dd], g_atl[(size_t)Bb * Ss * Dd];
__device__ __nv_bfloat16 g_wth[4 * 1024 * 1024], g_wtl[4 * 1024 * 1024];
__device__ __nv_bfloat16 g_insh[3 * 4194304], g_insl[3 * 4194304]; // split inputs

// ---------------------------------------------------------------------------
__device__ __forceinline__ uint32_t smem_u32(const void* p) {
    uint32_t a;
    asm("{ .reg .u64 t; cvta.to.shared.u64 t, %1; cvt.u32.u64 %0, t; }"
        : "=r"(a) : "l"(p));
    return a;
}

__device__ __forceinline__ void ldm_x4(uint32_t* r, uint32_t addr) {
    asm volatile("ldmatrix.sync.aligned.m8n8.x4.shared.b16 {%0,%1,%2,%3}, [%4];"
        : "=r"(r[0]), "=r"(r[1]), "=r"(r[2]), "=r"(r[3]) : "r"(addr));
}

__device__ __forceinline__ void ldm_x4_t(uint32_t* r, uint32_t addr) {
    asm volatile("ldmatrix.sync.aligned.m8n8.x4.trans.shared.b16 {%0,%1,%2,%3}, [%4];"
        : "=r"(r[0]), "=r"(r[1]), "=r"(r[2]), "=r"(r[3]) : "r"(addr));
}

__device__ __forceinline__ void mma_bf16(float* d, const uint32_t* a,
                                         const uint32_t* b) {
    asm volatile(
        "mma.sync.aligned.m16n8k16.row.col.f32.bf16.bf16.f32 "
        "{%0,%1,%2,%3}, {%4,%5,%6,%7}, {%8,%9}, {%0,%1,%2,%3};"
        : "+f"(d[0]), "+f"(d[1]), "+f"(d[2]), "+f"(d[3])
        : "r"(a[0]), "r"(a[1]), "r"(a[2]), "r"(a[3]), "r"(b[0]), "r"(b[1]));
}

__device__ __forceinline__ float ex2(float x) {   // raw MUFU exp2
    float y;
    asm("ex2.approx.f32 %0, %1;" : "=f"(y) : "f"(x));
    return y;
}

// .cg: bypass L1 (fills shouldn't pollute the L1 ldmatrix uses)
#define CP16(dst, src) \
    asm volatile("cp.async.cg.shared.global [%0], [%1], 16;" \
        :: "r"((uint32_t)(dst)), "l"(src) : "memory")
#define CP_COMMIT() asm volatile("cp.async.commit_group;" ::: "memory")
#define CP_WAIT0()  asm volatile("cp.async.wait_group 0;" ::: "memory")

__device__ __forceinline__ uint32_t pack2(__nv_bfloat16 a, __nv_bfloat16 b) {
    return (uint32_t)__bfloat16_as_ushort(a) |
           ((uint32_t)__bfloat16_as_ushort(b) << 16);
}

__device__ __forceinline__ void split4(float4 x, __nv_bfloat16* hp,
                                       __nv_bfloat16* lp) {
    ushort4 hu, lu;
    __nv_bfloat16 h;
    h = __float2bfloat16_rn(x.x); hu.x = __bfloat16_as_ushort(h);
    lu.x = __bfloat16_as_ushort(__float2bfloat16_rn(x.x - __bfloat162float(h)));
    h = __float2bfloat16_rn(x.y); hu.y = __bfloat16_as_ushort(h);
    lu.y = __bfloat16_as_ushort(__float2bfloat16_rn(x.y - __bfloat162float(h)));
    h = __float2bfloat16_rn(x.z); hu.z = __bfloat16_as_ushort(h);
    lu.z = __bfloat16_as_ushort(__float2bfloat16_rn(x.z - __bfloat162float(h)));
    h = __float2bfloat16_rn(x.w); hu.w = __bfloat16_as_ushort(h);
    lu.w = __bfloat16_as_ushort(__float2bfloat16_rn(x.w - __bfloat162float(h)));
    *(ushort4*)hp = hu;
    *(ushort4*)lp = lu;
}

// ---------------------------------------------------------------------------
// Fused prep: z=0..3 weight transpose+split, z=4..6 input split.
// ---------------------------------------------------------------------------
__global__ void prep_all(const float* __restrict__ W0,
                         const float* __restrict__ W1,
                         const float* __restrict__ W2,
                         const float* __restrict__ W3,
                         const float* __restrict__ X0,
                         const float* __restrict__ X1,
                         const float* __restrict__ X2,
                         __nv_bfloat16* __restrict__ Wth,
                         __nv_bfloat16* __restrict__ Wtl)
{
    const int z = blockIdx.z;
    if (z < 4) {
        __shared__ float t[32][33];
        const float* W = (z == 0) ? W0 : (z == 1) ? W1 : (z == 2) ? W2 : W3;
        __nv_bfloat16* oh = Wth + (size_t)z * 1048576;
        __nv_bfloat16* ol = Wtl + (size_t)z * 1048576;
        const int tx = threadIdx.x & 31;
        const int ty4 = threadIdx.x >> 5;   // 0..7
        const int bx = blockIdx.x * 32, by = blockIdx.y * 32;
        #pragma unroll
        for (int i = ty4; i < 32; i += 8)
            t[i][tx] = W[(size_t)(by + i) * 1024 + bx + tx];
        __syncthreads();
        #pragma unroll
        for (int i = ty4; i < 32; i += 8) {
            const float v = t[tx][i];
            const __nv_bfloat16 h = __float2bfloat16_rn(v);
            const size_t idx = (size_t)(bx + i) * 1024 + by + tx;
            oh[idx] = h;
            ol[idx] = __float2bfloat16_rn(v - __bfloat162float(h));
        }
    } else {
        const int zz = z - 4;
        const float* X = (zz == 0) ? X0 : (zz == 1) ? X1 : X2;
        __nv_bfloat16* oh = g_insh + (size_t)zz * 4194304;
        __nv_bfloat16* ol = g_insl + (size_t)zz * 4194304;
        const int blk = blockIdx.y * 32 + blockIdx.x;
        const size_t e = ((size_t)blk * 256 + threadIdx.x) * 16;
        #pragma unroll
        for (int i = 0; i < 4; ++i) {
            const size_t ee = e + i * 4;
            split4(*(const float4*)(X + ee), oh + ee, ol + ee);
        }
    }
}

// ---------------------------------------------------------------------------
// Error-compensated bf16 mma.sync GEMM (128x128, 512 thr), A+B fragment
// double-buffering across kk, 2-stage cp.async, mid-phase fill issuance.
// FUSED=1: QKV fused, blockIdx.x = z*8 + ntile; rope for z<2; Q (z==0)
//          pre-scaled by 0.125*log2(e); bf16 head-split output.
// FUSED=0: single weight, fp32 row-major output to Cf.
// ---------------------------------------------------------------------------
#define GSTAGE (4 * 128 * GPAD)

template<int FUSED>
__global__ __launch_bounds__(512, 1) void gemm_mma(
    const __nv_bfloat16* __restrict__ Ahg_, const __nv_bfloat16* __restrict__ Alg_,
    const __nv_bfloat16* __restrict__ Wth, const __nv_bfloat16* __restrict__ Wtl,
    const float* __restrict__ b0, const float* __restrict__ b1,
    const float* __restrict__ b2, float* __restrict__ Cf,
    __nv_bfloat16* __restrict__ Ch0, __nv_bfloat16* __restrict__ Cl0,
    __nv_bfloat16* __restrict__ Ch1, __nv_bfloat16* __restrict__ Cl1,
    __nv_bfloat16* __restrict__ Ch2, __nv_bfloat16* __restrict__ Cl2)
{
    extern __shared__ __nv_bfloat16 smg[];
    __shared__ float sbias[128];

    const int tid = threadIdx.x;
    const int bx = blockIdx.x;
    const int z  = FUSED ? (bx >> 3) : 0;
    const int bn = FUSED ? ((bx & 7) * 128) : (bx * 128);
    const int bm = blockIdx.y * 128;

    const __nv_bfloat16* Ahg = FUSED ? Ahg_ + (size_t)z * 4194304 : Ahg_;
    const __nv_bfloat16* Alg = FUSED ? Alg_ + (size_t)z * 4194304 : Alg_;
    const __nv_bfloat16* Bth = Wth + (FUSED ? (size_t)z * 1048576 : 0);
    const __nv_bfloat16* Btl = Wtl + (FUSED ? (size_t)z * 1048576 : 0);
    const float* bias = FUSED ? (z == 0 ? b0 : (z == 1 ? b1 : b2)) : b0;

    if (tid < 128) sbias[tid] = bias[bn + tid];

    const int lane = tid & 31;
    const int w = tid >> 5;
    const int wm = w & 3;
    const int wn = w >> 2;

    const uint32_t sbase = smem_u32(smg);

    const int f_r = tid >> 3;
    const int f_c = (tid & 7) * 8;
    auto fill = [&](int stage, int chunk) {
        const int k0 = chunk * 64;
        const uint32_t sb = sbase + stage * GSTAGE * 2;
        #pragma unroll
        for (int i = 0; i < 2; ++i) {
            const int r = f_r + i * 64;
            const uint32_t so = (r * GPAD + f_c) * 2;
            CP16(sb + 0 * 128 * GPAD * 2 + so, Ahg + (size_t)(bm + r) * 1024 + k0 + f_c);
            CP16(sb + 1 * 128 * GPAD * 2 + so, Alg + (size_t)(bm + r) * 1024 + k0 + f_c);
            CP16(sb + 2 * 128 * GPAD * 2 + so, Bth + (size_t)(bn + r) * 1024 + k0 + f_c);
            CP16(sb + 3 * 128 * GPAD * 2 + so, Btl + (size_t)(bn + r) * 1024 + k0 + f_c);
        }
        CP_COMMIT();
    };

    float acc[2][4][4];
    #pragma unroll
    for (int mi = 0; mi < 2; mi++)
        #pragma unroll
        for (int ni = 0; ni < 4; ni++)
            #pragma unroll
            for (int q = 0; q < 4; q++) acc[mi][ni][q] = 0.f;

    const int a_row_l = (lane & 15);
    const int a_col_l = ((lane & 16) >> 1);
    const int b_row_l = (lane & 7) + ((lane & 16) >> 1);
    const int b_col_l = (lane & 8);

    fill(0, 0);

    for (int chunk = 0; chunk < 16; ++chunk) {
        const int st = chunk & 1;
        CP_WAIT0();
        __syncthreads();

        const uint32_t sAh = sbase + (st * GSTAGE + 0 * 128 * GPAD) * 2;
        const uint32_t sAl = sbase + (st * GSTAGE + 1 * 128 * GPAD) * 2;
        const uint32_t sBh = sbase + (st * GSTAGE + 2 * 128 * GPAD) * 2;
        const uint32_t sBl = sbase + (st * GSTAGE + 3 * 128 * GPAD) * 2;

        // double-buffered B and A fragments
        uint32_t BHf[2][4][2], BLf[2][4][2];
        uint32_t AHf[2][2][4], ALf[2][2][4];   // [buf][m-tile][frag]
        auto loadB = [&](int buf, int kkq) {
            const int kc = kkq * 16;
            #pragma unroll
            for (int nt = 0; nt < 2; ++nt) {
                const int row = wn * 32 + nt * 16 + b_row_l;
                const int col = kc + b_col_l;
                uint32_t r4[4];
                ldm_x4(r4, sBh + (row * GPAD + col) * 2);
                BHf[buf][nt*2][0] = r4[0]; BHf[buf][nt*2][1] = r4[1];
                BHf[buf][nt*2+1][0] = r4[2]; BHf[buf][nt*2+1][1] = r4[3];
                ldm_x4(r4, sBl + (row * GPAD + col) * 2);
                BLf[buf][nt*2][0] = r4[0]; BLf[buf][nt*2][1] = r4[1];
                BLf[buf][nt*2+1][0] = r4[2]; BLf[buf][nt*2+1][1] = r4[3];
            }
        };
        auto loadA = [&](int buf, int kkq) {
            const int col = kkq * 16 + a_col_l;
            ldm_x4(AHf[buf][0], sAh + ((wm * 32 + a_row_l) * GPAD + col) * 2);
            ldm_x4(ALf[buf][0], sAl + ((wm * 32 + a_row_l) * GPAD + col) * 2);
            ldm_x4(AHf[buf][1], sAh + ((wm * 32 + 16 + a_row_l) * GPAD + col) * 2);
            ldm_x4(ALf[buf][1], sAl + ((wm * 32 + 16 + a_row_l) * GPAD + col) * 2);
        };

        loadA(0, 0);
        loadB(0, 0);
        #pragma unroll
        for (int kk = 0; kk < 4; ++kk) {
            const int cur = kk & 1;
            // prefetch next kk's fragments before consuming current ones
            if (kk < 3) {
                loadA(cur ^ 1, kk + 1);
                loadB(cur ^ 1, kk + 1);
            }
            #pragma unroll
            for (int ni = 0; ni < 4; ++ni) {
                mma_bf16(acc[0][ni], AHf[cur][0], BHf[cur][ni]);
                mma_bf16(acc[1][ni], AHf[cur][1], BHf[cur][ni]);
            }
            #pragma unroll
            for (int ni = 0; ni < 4; ++ni) {
                mma_bf16(acc[0][ni], AHf[cur][0], BLf[cur][ni]);
                mma_bf16(acc[1][ni], AHf[cur][1], BLf[cur][ni]);
            }
            #pragma unroll
            for (int ni = 0; ni < 4; ++ni) {
                mma_bf16(acc[0][ni], ALf[cur][0], BHf[cur][ni]);
                mma_bf16(acc[1][ni], ALf[cur][1], BHf[cur][ni]);
            }
            // mid-phase fill: LSU burst issued after first MMA wave is queued
            if (kk == 0 && chunk + 1 < 16) fill(st ^ 1, chunk + 1);
        }
    }

    __nv_bfloat16* Ch = FUSED ? (z == 0 ? Ch0 : (z == 1 ? Ch1 : Ch2)) : Ch0;
    __nv_bfloat16* Cl = FUSED ? (z == 0 ? Cl0 : (z == 1 ? Cl1 : Cl2)) : Cl0;
    const bool do_rope = FUSED && (z < 2);
    // Fold QK scale AND log2(e) into Q so attention softmax runs in exp2 units.
    const float oscale = (FUSED && z == 0) ? 0.18033688011112042f : 1.0f;

    const int lr = lane >> 2;
    const int lc = (lane & 3) * 2;

    #pragma unroll
    for (int mi = 0; mi < 2; ++mi) {
        #pragma unroll
        for (int half = 0; half < 2; ++half) {
            const int m = bm + wm * 32 + mi * 16 + lr + half * 8;
            const int s_pos = m & (Ss - 1);
            const int b_idx = m >> 11;
            #pragma unroll
            for (int ni = 0; ni < 4; ++ni) {
                const int nl = wn * 32 + ni * 8 + lc;
                const int n = bn + nl;
                float f0 = acc[mi][ni][half * 2 + 0] + sbias[nl];
                float f1 = acc[mi][ni][half * 2 + 1] + sbias[nl + 1];

                if (do_rope) {
                    const int d0 = n & 63;
                    const int j0 = d0 & 31;
                    const int j1 = (d0 + 1) & 31;
                    const float inv0 = 1.0f / powf(10000.0f, (float)j0 * (1.0f / 32.0f));
                    const float inv1 = 1.0f / powf(10000.0f, (float)j1 * (1.0f / 32.0f));
                    float s0, c0, s1, c1;
                    sincosf((float)s_pos * inv0, &s0, &c0);
                    sincosf((float)s_pos * inv1, &s1, &c1);
                    const float x0 = f0, x1 = f1;
                    f0 = x0 * c0 - x1 * s1;
                    f1 = x0 * s0 + x1 * c1;
                }
                f0 *= oscale;
                f1 *= oscale;

                if (FUSED) {
                    const int h = n >> 6, d = n & 63;
                    const size_t idx =
                        (((size_t)b_idx * Hh + h) * Ss + s_pos) * DKk + d;
                    const __nv_bfloat16 h0 = __float2bfloat16_rn(f0);
                    const __nv_bfloat16 h1 = __float2bfloat16_rn(f1);
                    *(uint32_t*)(Ch + idx) = pack2(h0, h1);
                    *(uint32_t*)(Cl + idx) =
                        pack2(__float2bfloat16_rn(f0 - __bfloat162float(h0)),
                              __float2bfloat16_rn(f1 - __bfloat162float(h1)));
                } else {
                    *(float2*)(Cf + (size_t)m * Dd + n) = make_float2(f0, f1);
                }
            }
        }
    }
}

// ---------------------------------------------------------------------------
// Causal flash attention (unchanged from R12): frag-double-buffered, 128-key
// blocks, 2-stage cp.async, exp2-folded softmax, mid-iteration fill.
// ---------------------------------------------------------------------------
#define ASTAGE (4 * 128 * GPAD)

__global__ __launch_bounds__(256, 1) void attn_mma()
{
    extern __shared__ __nv_bfloat16 smb[];
    __nv_bfloat16* Qh = smb;
    __nv_bfloat16* Ql = Qh + 128 * GPAD;
    __nv_bfloat16* Stg = Ql + 128 * GPAD;

    const int qb = gridDim.x - 1 - blockIdx.x;
    const int bh = blockIdx.y;
    const int bidx = bh >> 4;
    const int head = bh & 15;
    const int tid = threadIdx.x;
    const int lane = tid & 31;
    const int w = tid >> 5;
    const int wq = w * 16;

    const __nv_bfloat16* qhg = g_qh + ((size_t)bh * Ss + (size_t)qb * 128) * DKk;
    const __nv_bfloat16* qlg = g_ql + ((size_t)bh * Ss + (size_t)qb * 128) * DKk;
    const __nv_bfloat16* khg = g_kh + (size_t)bh * Ss * DKk;
    const __nv_bfloat16* klg = g_kl + (size_t)bh * Ss * DKk;
    const __nv_bfloat16* vhg = g_vh + (size_t)bh * Ss * DKk;
    const __nv_bfloat16* vlg = g_vl + (size_t)bh * Ss * DKk;

    const uint32_t sQh = smem_u32(Qh), sQl = smem_u32(Ql);
    const uint32_t sStg = smem_u32(Stg);

    #pragma unroll
    for (int e = tid; e < 1024; e += 256) {
        const int r = e >> 3, c = (e & 7) * 8;
        *(uint4*)(Qh + r * GPAD + c) = *(const uint4*)(qhg + r * 64 + c);
        *(uint4*)(Ql + r * GPAD + c) = *(const uint4*)(qlg + r * 64 + c);
    }

    const int nkb = qb + 1;

    const int f_r = tid >> 3;
    const int f_c = (tid & 7) * 8;
    auto fill_stage = [&](int stage, int kb) {
        const size_t gofs = (size_t)kb * 128 * DKk;
        const uint32_t sb = sStg + stage * ASTAGE * 2;
        #pragma unroll
        for (int i = 0; i < 4; ++i) {
            const int r = f_r + i * 32;
            const uint32_t so = (r * GPAD + f_c) * 2;
            const size_t go = gofs + r * 64 + f_c;
            CP16(sb + 0 * 128 * GPAD * 2 + so, khg + go);
            CP16(sb + 1 * 128 * GPAD * 2 + so, klg + go);
            CP16(sb + 2 * 128 * GPAD * 2 + so, vhg + go);
            CP16(sb + 3 * 128 * GPAD * 2 + so, vlg + go);
        }
        CP_COMMIT();
    };

    fill_stage(0, 0);
    __syncthreads();

    const int a_row = lane & 15;
    const int a_col = (lane & 16) >> 1;
    const int b_row = (lane & 7) + ((lane & 16) >> 1);
    const int b_col = lane & 8;
    const int v_key = ((lane >> 3) & 1) * 8 + (lane & 7);
    const int v_dim = (lane >> 4) * 8;

    uint32_t qfh[4][4], qfl[4][4];
    #pragma unroll
    for (int kt = 0; kt < 4; ++kt) {
        const uint32_t off = ((wq + a_row) * GPAD + kt * 16 + a_col) * 2;
        ldm_x4(qfh[kt], sQh + off);
        ldm_x4(qfl[kt], sQl + off);
    }

    float O[8][4];
    #pragma unroll
    for (int nf = 0; nf < 8; ++nf)
        #pragma unroll
        for (int j = 0; j < 4; ++j) O[nf][j] = 0.f;
    float mrow[2] = {-INFINITY, -INFINITY};
    float lrow[2] = {0.f, 0.f};

    const int lr = lane >> 2;
    const int lc2 = (lane & 3) * 2;
    const int q0 = qb * 128 + wq + lr;

    for (int kb = 0; kb < nkb; ++kb) {
        const int st = kb & 1;
        CP_WAIT0();
        __syncthreads();

        const uint32_t sKh = sStg + (st * ASTAGE + 0 * 128 * GPAD) * 2;
        const uint32_t sKl = sStg + (st * ASTAGE + 1 * 128 * GPAD) * 2;
        const uint32_t sVh = sStg + (st * ASTAGE + 2 * 128 * GPAD) * 2;
        const uint32_t sVl = sStg + (st * ASTAGE + 3 * 128 * GPAD) * 2;

        // ---- scores = Q K^T (Q pre-scaled into log2 units) ----
        float acc[16][4];
        #pragma unroll
        for (int nf = 0; nf < 16; ++nf)
            #pragma unroll
            for (int j = 0; j < 4; ++j) acc[nf][j] = 0.f;

        {
            uint32_t KHf[2][2][2], KLf[2][2][2];
            auto loadK = [&](int buf, int it2) {
                const int kt2 = it2 >> 3, ntp2 = it2 & 7;
                const uint32_t off =
                    ((ntp2 * 16 + b_row) * GPAD + kt2 * 16 + b_col) * 2;
                uint32_t r4[4];
                ldm_x4(r4, sKh + off);
                KHf[buf][0][0] = r4[0]; KHf[buf][0][1] = r4[1];
                KHf[buf][1][0] = r4[2]; KHf[buf][1][1] = r4[3];
                ldm_x4(r4, sKl + off);
                KLf[buf][0][0] = r4[0]; KLf[buf][0][1] = r4[1];
                KLf[buf][1][0] = r4[2]; KLf[buf][1][1] = r4[3];
            };
            loadK(0, 0);
            #pragma unroll
            for (int it = 0; it < 32; ++it) {
                const int kt = it >> 3, ntp = it & 7, cur = it & 1;
                if (it < 31) loadK(cur ^ 1, it + 1);
                mma_bf16(acc[2*ntp],   qfh[kt], KHf[cur][0]);
                mma_bf16(acc[2*ntp+1], qfh[kt], KHf[cur][1]);
                mma_bf16(acc[2*ntp],   qfh[kt], KLf[cur][0]);
                mma_bf16(acc[2*ntp+1], qfh[kt], KLf[cur][1]);
                mma_bf16(acc[2*ntp],   qfl[kt], KHf[cur][0]);
                mma_bf16(acc[2*ntp+1], qfl[kt], KHf[cur][1]);
            }
        }

        // mid-iteration fill: hidden behind softmax ALU/MUFU work
        if (kb + 1 < nkb) fill_stage(st ^ 1, kb + 1);

        // ---- causal mask ----
        if (kb == qb) {
            #pragma unroll
            for (int nf = 0; nf < 16; ++nf) {
                #pragma unroll
                for (int j = 0; j < 4; ++j) {
                    const int kgl = kb * 128 + nf * 8 + lc2 + (j & 1);
                    const int qgl = q0 + 8 * (j >> 1);
                    if (kgl > qgl) acc[nf][j] = -1e30f;
                }
            }
        }

        // ---- online softmax in log2 units (per row-half) ----
        #pragma unroll
        for (int half = 0; half < 2; ++half) {
            float rm = -1e30f;
            #pragma unroll
            for (int nf = 0; nf < 16; ++nf)
                rm = fmaxf(rm, fmaxf(acc[nf][2*half], acc[nf][2*half+1]));
            rm = fmaxf(rm, __shfl_xor_sync(0xffffffffu, rm, 1));
            rm = fmaxf(rm, __shfl_xor_sync(0xffffffffu, rm, 2));
            const float mn = fmaxf(mrow[half], rm);
            const float alpha = ex2(mrow[half] - mn);
            mrow[half] = mn;
            float rs = 0.f;
            #pragma unroll
            for (int nf = 0; nf < 16; ++nf) {
                const float p0 = ex2(acc[nf][2*half]   - mn);
                const float p1 = ex2(acc[nf][2*half+1] - mn);
                acc[nf][2*half]   = p0;
                acc[nf][2*half+1] = p1;
                rs += p0 + p1;
            }
            rs += __shfl_xor_sync(0xffffffffu, rs, 1);
            rs += __shfl_xor_sync(0xffffffffu, rs, 2);
            lrow[half] = lrow[half] * alpha + rs;
            #pragma unroll
            for (int nf = 0; nf < 8; ++nf) {
                O[nf][2*half]   *= alpha;
                O[nf][2*half+1] *= alpha;
            }
        }

        // ---- O += P V ----
        {
            uint32_t VHf[2][2][2], VLf[2][2][2];
            uint32_t ah[4], al[4];
            auto loadV = [&](int buf, int it2) {
                const int kt2 = it2 >> 2, nd2 = it2 & 3;
                const uint32_t off =
                    ((kt2 * 16 + v_key) * GPAD + nd2 * 16 + v_dim) * 2;
                uint32_t r4[4];
                ldm_x4_t(r4, sVh + off);
                VHf[buf][0][0] = r4[0]; VHf[buf][0][1] = r4[1];
                VHf[buf][1][0] = r4[2]; VHf[buf][1][1] = r4[3];
                ldm_x4_t(r4, sVl + off);
                VLf[buf][0][0] = r4[0]; VLf[buf][0][1] = r4[1];
                VLf[buf][1][0] = r4[2]; VLf[buf][1][1] = r4[3];
            };
            auto packP = [&](int kt) {
                #pragma unroll
                for (int f = 0; f < 4; ++f) {
                    const float p0 = acc[2*kt + (f >> 1)][(f & 1) * 2 + 0];
                    const float p1 = acc[2*kt + (f >> 1)][(f & 1) * 2 + 1];
                    const __nv_bfloat16 h0 = __float2bfloat16_rn(p0);
                    const __nv_bfloat16 h1 = __float2bfloat16_rn(p1);
                    ah[f] = pack2(h0, h1);
                    al[f] = pack2(__float2bfloat16_rn(p0 - __bfloat162float(h0)),
                                  __float2bfloat16_rn(p1 - __bfloat162float(h1)));
                }
            };
            packP(0);
            loadV(0, 0);
            #pragma unroll
            for (int it = 0; it < 32; ++it) {
                const int kt = it >> 2, nd = it & 3, cur = it & 1;
                if (it < 31) loadV(cur ^ 1, it + 1);
                mma_bf16(O[2*nd],   ah, VHf[cur][0]);
                mma_bf16(O[2*nd+1], ah, VHf[cur][1]);
                mma_bf16(O[2*nd],   ah, VLf[cur][0]);
                mma_bf16(O[2*nd+1], ah, VLf[cur][1]);
                mma_bf16(O[2*nd],   al, VHf[cur][0]);
                mma_bf16(O[2*nd+1], al, VHf[cur][1]);
                if (nd == 3 && kt < 7) packP(kt + 1);
            }
        }
    }

    // ---- normalize + split-store ----
    #pragma unroll
    for (int half = 0; half < 2; ++half) {
        const int qgl = q0 + 8 * half;
        const float inv = 1.0f / lrow[half];
        const size_t base = ((size_t)bidx * Ss + qgl) * Dd + head * 64;
        #pragma unroll
        for (int nf = 0; nf < 8; ++nf) {
            const float f0 = O[nf][2*half] * inv;
            const float f1 = O[nf][2*half+1] * inv;
            const __nv_bfloat16 h0 = __float2bfloat16_rn(f0);
            const __nv_bfloat16 h1 = __float2bfloat16_rn(f1);
            *(uint32_t*)(g_ath + base + nf * 8 + lc2) = pack2(h0, h1);
            *(uint32_t*)(g_atl + base + nf * 8 + lc2) =
                pack2(__float2bfloat16_rn(f0 - __bfloat162float(h0)),
                      __float2bfloat16_rn(f1 - __bfloat162float(h1)));
        }
    }
}

// ---------------------------------------------------------------------------
extern "C" void kernel_launch(void* const* d_in, const int* in_sizes, int n_in,
                              void* d_out, int out_size)
{
    const float* query = (const float*)d_in[0];
    const float* key   = (const float*)d_in[1];
    const float* value = (const float*)d_in[2];
    const float* Wq = (const float*)d_in[3];
    const float* bq = (const float*)d_in[4];
    const float* Wk = (const float*)d_in[5];
    const float* bk = (const float*)d_in[6];
    const float* Wv = (const float*)d_in[7];
    const float* bv = (const float*)d_in[8];
    const float* Wo = (const float*)d_in[9];
    const float* bo = (const float*)d_in[10];
    float* out = (float*)d_out;

    __nv_bfloat16 *qh, *ql, *kh, *kl, *vh, *vl, *ath, *atl, *wth, *wtl, *ish, *isl;
    cudaGetSymbolAddress((void**)&qh, g_qh);
    cudaGetSymbolAddress((void**)&ql, g_ql);
    cudaGetSymbolAddress((void**)&kh, g_kh);
    cudaGetSymbolAddress((void**)&kl, g_kl);
    cudaGetSymbolAddress((void**)&vh, g_vh);
    cudaGetSymbolAddress((void**)&vl, g_vl);
    cudaGetSymbolAddress((void**)&ath, g_ath);
    cudaGetSymbolAddress((void**)&atl, g_atl);
    cudaGetSymbolAddress((void**)&wth, g_wth);
    cudaGetSymbolAddress((void**)&wtl, g_wtl);
    cudaGetSymbolAddress((void**)&ish, g_insh);
    cudaGetSymbolAddress((void**)&isl, g_insl);

    // Fused prep: weights transpose+split (z=0..3) + input split (z=4..6)
    prep_all<<<dim3(32, 32, 7), 256>>>(Wq, Wk, Wv, Wo, query, key, value,
                                       wth, wtl);

    const int gsmem = 2 * GSTAGE * (int)sizeof(__nv_bfloat16);   // 147456
    cudaFuncSetAttribute(gemm_mma<1>, cudaFuncAttributeMaxDynamicSharedMemorySize, gsmem);
    cudaFuncSetAttribute(gemm_mma<0>, cudaFuncAttributeMaxDynamicSharedMemorySize, gsmem);

    // Fused QKV projection: grid.x = 3 weights x 8 n-tiles
    gemm_mma<1><<<dim3(24, 32), 512, gsmem>>>(
        ish, isl, wth, wtl, bq, bk, bv, nullptr,
        qh, ql, kh, kl, vh, vl);

    const int asmem = (2 * 128 * GPAD + 2 * ASTAGE) *
                      (int)sizeof(__nv_bfloat16);   // 184320
    cudaFuncSetAttribute(attn_mma, cudaFuncAttributeMaxDynamicSharedMemorySize, asmem);
    attn_mma<<<dim3(Ss / 128, Bb * Hh), 256, asmem>>>();

    // Output projection (fp32 out)
    gemm_mma<0><<<dim3(8, 32), 512, gsmem>>>(
        ath, atl, wth + 3u * 1048576, wtl + 3u * 1048576, bo, nullptr, nullptr,
        out, nullptr, nullptr, nullptr, nullptr, nullptr, nullptr);
}

// round 14
// speedup vs baseline: 1.0378x; 1.0378x over previous
#include <cuda_runtime.h>
#include <cuda_bf16.h>
#include <math.h>
#include <stdint.h>

#define Bb 2
#define Ss 2048
#define Dd 1024
#define Hh 16
#define DKk 64
#define GPAD 72   // bf16 columns per SMEM row (144 B stride, ldmatrix conflict-free)

// Scratch (device globals: allocation-free rule). All pre-split bf16 hi/lo.
#define QKV_ELEMS ((size_t)Bb * Hh * Ss * DKk)
__device__ __nv_bfloat16 g_qh[QKV_ELEMS], g_ql[QKV_ELEMS];
__device__ __nv_bfloat16 g_kh[QKV_ELEMS], g_kl[QKV_ELEMS];
__device__ __nv_bfloat16 g_vh[QKV_ELEMS], g_vl[QKV_ELEMS];
__device__ __nv_bfloat16 g_ath[(size_t)Bb * Ss * Dd], g_atl[(size_t)Bb * Ss * Dd];
__device__ __nv_bfloat16 g_wth[4 * 1024 * 1024], g_wtl[4 * 1024 * 1024];
__device__ __nv_bfloat16 g_insh[3 * 4194304], g_insl[3 * 4194304]; // split inputs
__device__ float g_rope[Ss * DKk * 2];   // (cos,sin) per (s, d); 1 MB

// ---------------------------------------------------------------------------
__device__ __forceinline__ uint32_t smem_u32(const void* p) {
    uint32_t a;
    asm("{ .reg .u64 t; cvta.to.shared.u64 t, %1; cvt.u32.u64 %0, t; }"
        : "=r"(a) : "l"(p));
    return a;
}

__device__ __forceinline__ void ldm_x4(uint32_t* r, uint32_t addr) {
    asm volatile("ldmatrix.sync.aligned.m8n8.x4.shared.b16 {%0,%1,%2,%3}, [%4];"
        : "=r"(r[0]), "=r"(r[1]), "=r"(r[2]), "=r"(r[3]) : "r"(addr));
}

__device__ __forceinline__ void ldm_x4_t(uint32_t* r, uint32_t addr) {
    asm volatile("ldmatrix.sync.aligned.m8n8.x4.trans.shared.b16 {%0,%1,%2,%3}, [%4];"
        : "=r"(r[0]), "=r"(r[1]), "=r"(r[2]), "=r"(r[3]) : "r"(addr));
}

__device__ __forceinline__ void mma_bf16(float* d, const uint32_t* a,
                                         const uint32_t* b) {
    asm volatile(
        "mma.sync.aligned.m16n8k16.row.col.f32.bf16.bf16.f32 "
        "{%0,%1,%2,%3}, {%4,%5,%6,%7}, {%8,%9}, {%0,%1,%2,%3};"
        : "+f"(d[0]), "+f"(d[1]), "+f"(d[2]), "+f"(d[3])
        : "r"(a[0]), "r"(a[1]), "r"(a[2]), "r"(a[3]), "r"(b[0]), "r"(b[1]));
}

__device__ __forceinline__ float ex2(float x) {   // raw MUFU exp2
    float y;
    asm("ex2.approx.f32 %0, %1;" : "=f"(y) : "f"(x));
    return y;
}

// pack two f32 into bf16x2 with .rn (same rounding as __float2bfloat16_rn)
__device__ __forceinline__ uint32_t cvt2_bf16(float lo, float hi) {
    uint32_t r;
    asm("cvt.rn.bf16x2.f32 %0, %1, %2;" : "=r"(r) : "f"(hi), "f"(lo));
    return r;
}

// split two floats into packed hi + packed lo (bit-identical to split4 path)
__device__ __forceinline__ void split2_pack(float p0, float p1,
                                            uint32_t& hh, uint32_t& ll) {
    hh = cvt2_bf16(p0, p1);
    const float h0f = __uint_as_float(hh << 16);
    const float h1f = __uint_as_float(hh & 0xffff0000u);
    ll = cvt2_bf16(p0 - h0f, p1 - h1f);
}

// .cg: bypass L1 (fills shouldn't pollute the L1 ldmatrix uses)
#define CP16(dst, src) \
    asm volatile("cp.async.cg.shared.global [%0], [%1], 16;" \
        :: "r"((uint32_t)(dst)), "l"(src) : "memory")
#define CP_COMMIT() asm volatile("cp.async.commit_group;" ::: "memory")
#define CP_WAIT0()  asm volatile("cp.async.wait_group 0;" ::: "memory")

__device__ __forceinline__ void split4(float4 x, __nv_bfloat16* hp,
                                       __nv_bfloat16* lp) {
    ushort4 hu, lu;
    __nv_bfloat16 h;
    h = __float2bfloat16_rn(x.x); hu.x = __bfloat16_as_ushort(h);
    lu.x = __bfloat16_as_ushort(__float2bfloat16_rn(x.x - __bfloat162float(h)));
    h = __float2bfloat16_rn(x.y); hu.y = __bfloat16_as_ushort(h);
    lu.y = __bfloat16_as_ushort(__float2bfloat16_rn(x.y - __bfloat162float(h)));
    h = __float2bfloat16_rn(x.z); hu.z = __bfloat16_as_ushort(h);
    lu.z = __bfloat16_as_ushort(__float2bfloat16_rn(x.z - __bfloat162float(h)));
    h = __float2bfloat16_rn(x.w); hu.w = __bfloat16_as_ushort(h);
    lu.w = __bfloat16_as_ushort(__float2bfloat16_rn(x.w - __bfloat162float(h)));
    *(ushort4*)hp = hu;
    *(ushort4*)lp = lu;
}

// ---------------------------------------------------------------------------
// Fused prep: z=0..3 weight transpose+split, z=4..6 input split,
// z=7 rope cos/sin table (bit-identical formulas to the old epilogue).
// ---------------------------------------------------------------------------
__global__ void prep_all(const float* __restrict__ W0,
                         const float* __restrict__ W1,
                         const float* __restrict__ W2,
                         const float* __restrict__ W3,
                         const float* __restrict__ X0,
                         const float* __restrict__ X1,
                         const float* __restrict__ X2,
                         __nv_bfloat16* __restrict__ Wth,
                         __nv_bfloat16* __restrict__ Wtl)
{
    const int z = blockIdx.z;
    if (z < 4) {
        __shared__ float t[32][33];
        const float* W = (z == 0) ? W0 : (z == 1) ? W1 : (z == 2) ? W2 : W3;
        __nv_bfloat16* oh = Wth + (size_t)z * 1048576;
        __nv_bfloat16* ol = Wtl + (size_t)z * 1048576;
        const int tx = threadIdx.x & 31;
        const int ty4 = threadIdx.x >> 5;   // 0..7
        const int bx = blockIdx.x * 32, by = blockIdx.y * 32;
        #pragma unroll
        for (int i = ty4; i < 32; i += 8)
            t[i][tx] = W[(size_t)(by + i) * 1024 + bx + tx];
        __syncthreads();
        #pragma unroll
        for (int i = ty4; i < 32; i += 8) {
            const float v = t[tx][i];
            const __nv_bfloat16 h = __float2bfloat16_rn(v);
            const size_t idx = (size_t)(bx + i) * 1024 + by + tx;
            oh[idx] = h;
            ol[idx] = __float2bfloat16_rn(v - __bfloat162float(h));
        }
    } else if (z < 7) {
        const int zz = z - 4;
        const float* X = (zz == 0) ? X0 : (zz == 1) ? X1 : X2;
        __nv_bfloat16* oh = g_insh + (size_t)zz * 4194304;
        __nv_bfloat16* ol = g_insl + (size_t)zz * 4194304;
        const int blk = blockIdx.y * 32 + blockIdx.x;
        const size_t e = ((size_t)blk * 256 + threadIdx.x) * 16;
        #pragma unroll
        for (int i = 0; i < 4; ++i) {
            const size_t ee = e + i * 4;
            split4(*(const float4*)(X + ee), oh + ee, ol + ee);
        }
    } else {
        // rope table: cs[s][d] = (cos(s*inv(j)), sin(s*inv(j))), j = d & 31
        const int idx = (blockIdx.y * 32 + blockIdx.x) * 256 + threadIdx.x;
        if (idx < Ss * DKk) {
            const int s = idx >> 6, d = idx & 63, j = d & 31;
            const float inv = 1.0f / powf(10000.0f, (float)j * (1.0f / 32.0f));
            float sn, cn;
            sincosf((float)s * inv, &sn, &cn);
            g_rope[(size_t)idx * 2 + 0] = cn;
            g_rope[(size_t)idx * 2 + 1] = sn;
        }
    }
}

// ---------------------------------------------------------------------------
// Error-compensated bf16 mma.sync GEMM (R12 mainloop: 128x128, 512 thr),
// frag-double-buffered B, 2-stage cp.async, mid-phase fill issuance.
// FUSED=1: QKV fused, blockIdx.x = z*8 + ntile; rope (table) for z<2;
//          Q (z==0) pre-scaled by 0.125*log2(e); bf16 head-split output.
// FUSED=0: single weight, fp32 row-major output to Cf.
// ---------------------------------------------------------------------------
#define GSTAGE (4 * 128 * GPAD)

template<int FUSED>
__global__ __launch_bounds__(512, 1) void gemm_mma(
    const __nv_bfloat16* __restrict__ Ahg_, const __nv_bfloat16* __restrict__ Alg_,
    const __nv_bfloat16* __restrict__ Wth, const __nv_bfloat16* __restrict__ Wtl,
    const float* __restrict__ b0, const float* __restrict__ b1,
    const float* __restrict__ b2, float* __restrict__ Cf,
    __nv_bfloat16* __restrict__ Ch0, __nv_bfloat16* __restrict__ Cl0,
    __nv_bfloat16* __restrict__ Ch1, __nv_bfloat16* __restrict__ Cl1,
    __nv_bfloat16* __restrict__ Ch2, __nv_bfloat16* __restrict__ Cl2)
{
    extern __shared__ __nv_bfloat16 smg[];
    __shared__ float sbias[128];

    const int tid = threadIdx.x;
    const int bx = blockIdx.x;
    const int z  = FUSED ? (bx >> 3) : 0;
    const int bn = FUSED ? ((bx & 7) * 128) : (bx * 128);
    const int bm = blockIdx.y * 128;

    const __nv_bfloat16* Ahg = FUSED ? Ahg_ + (size_t)z * 4194304 : Ahg_;
    const __nv_bfloat16* Alg = FUSED ? Alg_ + (size_t)z * 4194304 : Alg_;
    const __nv_bfloat16* Bth = Wth + (FUSED ? (size_t)z * 1048576 : 0);
    const __nv_bfloat16* Btl = Wtl + (FUSED ? (size_t)z * 1048576 : 0);
    const float* bias = FUSED ? (z == 0 ? b0 : (z == 1 ? b1 : b2)) : b0;

    if (tid < 128) sbias[tid] = bias[bn + tid];

    const int lane = tid & 31;
    const int w = tid >> 5;
    const int wm = w & 3;
    const int wn = w >> 2;

    const uint32_t sbase = smem_u32(smg);

    const int f_r = tid >> 3;
    const int f_c = (tid & 7) * 8;
    auto fill = [&](int stage, int chunk) {
        const int k0 = chunk * 64;
        const uint32_t sb = sbase + stage * GSTAGE * 2;
        #pragma unroll
        for (int i = 0; i < 2; ++i) {
            const int r = f_r + i * 64;
            const uint32_t so = (r * GPAD + f_c) * 2;
            CP16(sb + 0 * 128 * GPAD * 2 + so, Ahg + (size_t)(bm + r) * 1024 + k0 + f_c);
            CP16(sb + 1 * 128 * GPAD * 2 + so, Alg + (size_t)(bm + r) * 1024 + k0 + f_c);
            CP16(sb + 2 * 128 * GPAD * 2 + so, Bth + (size_t)(bn + r) * 1024 + k0 + f_c);
            CP16(sb + 3 * 128 * GPAD * 2 + so, Btl + (size_t)(bn + r) * 1024 + k0 + f_c);
        }
        CP_COMMIT();
    };

    float acc[2][4][4];
    #pragma unroll
    for (int mi = 0; mi < 2; mi++)
        #pragma unroll
        for (int ni = 0; ni < 4; ni++)
            #pragma unroll
            for (int q = 0; q < 4; q++) acc[mi][ni][q] = 0.f;

    const int a_row_l = (lane & 15);
    const int a_col_l = ((lane & 16) >> 1);
    const int b_row_l = (lane & 7) + ((lane & 16) >> 1);
    const int b_col_l = (lane & 8);

    fill(0, 0);

    for (int chunk = 0; chunk < 16; ++chunk) {
        const int st = chunk & 1;
        CP_WAIT0();
        __syncthreads();

        const uint32_t sAh = sbase + (st * GSTAGE + 0 * 128 * GPAD) * 2;
        const uint32_t sAl = sbase + (st * GSTAGE + 1 * 128 * GPAD) * 2;
        const uint32_t sBh = sbase + (st * GSTAGE + 2 * 128 * GPAD) * 2;
        const uint32_t sBl = sbase + (st * GSTAGE + 3 * 128 * GPAD) * 2;

        uint32_t BHf[2][4][2], BLf[2][4][2];
        auto loadB = [&](int buf, int kkq) {
            const int kc = kkq * 16;
            #pragma unroll
            for (int nt = 0; nt < 2; ++nt) {
                const int row = wn * 32 + nt * 16 + b_row_l;
                const int col = kc + b_col_l;
                uint32_t r4[4];
                ldm_x4(r4, sBh + (row * GPAD + col) * 2);
                BHf[buf][nt*2][0] = r4[0]; BHf[buf][nt*2][1] = r4[1];
                BHf[buf][nt*2+1][0] = r4[2]; BHf[buf][nt*2+1][1] = r4[3];
                ldm_x4(r4, sBl + (row * GPAD + col) * 2);
                BLf[buf][nt*2][0] = r4[0]; BLf[buf][nt*2][1] = r4[1];
                BLf[buf][nt*2+1][0] = r4[2]; BLf[buf][nt*2+1][1] = r4[3];
            }
        };

        loadB(0, 0);
        #pragma unroll
        for (int kk = 0; kk < 4; ++kk) {
            const int cur = kk & 1;
            const int col = kk * 16 + a_col_l;
            uint32_t ah0[4], al0[4], ah1[4], al1[4];
            ldm_x4(ah0, sAh + ((wm * 32 + a_row_l) * GPAD + col) * 2);
            ldm_x4(al0, sAl + ((wm * 32 + a_row_l) * GPAD + col) * 2);
            ldm_x4(ah1, sAh + ((wm * 32 + 16 + a_row_l) * GPAD + col) * 2);
            ldm_x4(al1, sAl + ((wm * 32 + 16 + a_row_l) * GPAD + col) * 2);
            if (kk < 3) loadB(cur ^ 1, kk + 1);
            #pragma unroll
            for (int ni = 0; ni < 4; ++ni) {
                mma_bf16(acc[0][ni], ah0, BHf[cur][ni]);
                mma_bf16(acc[1][ni], ah1, BHf[cur][ni]);
            }
            #pragma unroll
            for (int ni = 0; ni < 4; ++ni) {
                mma_bf16(acc[0][ni], ah0, BLf[cur][ni]);
                mma_bf16(acc[1][ni], ah1, BLf[cur][ni]);
            }
            #pragma unroll
            for (int ni = 0; ni < 4; ++ni) {
                mma_bf16(acc[0][ni], al0, BHf[cur][ni]);
                mma_bf16(acc[1][ni], al1, BHf[cur][ni]);
            }
            // mid-phase fill: LSU burst issued after first MMA wave is queued
            if (kk == 0 && chunk + 1 < 16) fill(st ^ 1, chunk + 1);
        }
    }

    __nv_bfloat16* Ch = FUSED ? (z == 0 ? Ch0 : (z == 1 ? Ch1 : Ch2)) : Ch0;
    __nv_bfloat16* Cl = FUSED ? (z == 0 ? Cl0 : (z == 1 ? Cl1 : Cl2)) : Cl0;
    const bool do_rope = FUSED && (z < 2);
    // Fold QK scale AND log2(e) into Q so attention softmax runs in exp2 units.
    const float oscale = (FUSED && z == 0) ? 0.18033688011112042f : 1.0f;

    const int lr = lane >> 2;
    const int lc = (lane & 3) * 2;

    #pragma unroll
    for (int mi = 0; mi < 2; ++mi) {
        #pragma unroll
        for (int half = 0; half < 2; ++half) {
            const int m = bm + wm * 32 + mi * 16 + lr + half * 8;
            const int s_pos = m & (Ss - 1);
            const int b_idx = m >> 11;
            #pragma unroll
            for (int ni = 0; ni < 4; ++ni) {
                const int nl = wn * 32 + ni * 8 + lc;
                const int n = bn + nl;
                float f0 = acc[mi][ni][half * 2 + 0] + sbias[nl];
                float f1 = acc[mi][ni][half * 2 + 1] + sbias[nl + 1];

                if (do_rope) {
                    // table lookup: (cos,sin) for d0 and d0+1 in one float4
                    const int d0 = n & 63;
                    const float4 cs = *(const float4*)(
                        g_rope + ((size_t)s_pos * 64 + d0) * 2);
                    const float x0 = f0, x1 = f1;
                    f0 = x0 * cs.x - x1 * cs.w;
                    f1 = x0 * cs.y + x1 * cs.z;
                }
                f0 *= oscale;
                f1 *= oscale;

                if (FUSED) {
                    const int h = n >> 6, d = n & 63;
                    const size_t idx =
                        (((size_t)b_idx * Hh + h) * Ss + s_pos) * DKk + d;
                    uint32_t hh, ll;
                    split2_pack(f0, f1, hh, ll);
                    *(uint32_t*)(Ch + idx) = hh;
                    *(uint32_t*)(Cl + idx) = ll;
                } else {
                    *(float2*)(Cf + (size_t)m * Dd + n) = make_float2(f0, f1);
                }
            }
        }
    }
}

// ---------------------------------------------------------------------------
// Causal flash attention: frag-double-buffered, 128-key blocks, 2-stage
// cp.async, exp2-folded softmax, mid-iteration fill, fast bf16x2 packing.
// ---------------------------------------------------------------------------
#define ASTAGE (4 * 128 * GPAD)

__global__ __launch_bounds__(256, 1) void attn_mma()
{
    extern __shared__ __nv_bfloat16 smb[];
    __nv_bfloat16* Qh = smb;
    __nv_bfloat16* Ql = Qh + 128 * GPAD;
    __nv_bfloat16* Stg = Ql + 128 * GPAD;

    const int qb = gridDim.x - 1 - blockIdx.x;
    const int bh = blockIdx.y;
    const int bidx = bh >> 4;
    const int head = bh & 15;
    const int tid = threadIdx.x;
    const int lane = tid & 31;
    const int w = tid >> 5;
    const int wq = w * 16;

    const __nv_bfloat16* qhg = g_qh + ((size_t)bh * Ss + (size_t)qb * 128) * DKk;
    const __nv_bfloat16* qlg = g_ql + ((size_t)bh * Ss + (size_t)qb * 128) * DKk;
    const __nv_bfloat16* khg = g_kh + (size_t)bh * Ss * DKk;
    const __nv_bfloat16* klg = g_kl + (size_t)bh * Ss * DKk;
    const __nv_bfloat16* vhg = g_vh + (size_t)bh * Ss * DKk;
    const __nv_bfloat16* vlg = g_vl + (size_t)bh * Ss * DKk;

    const uint32_t sQh = smem_u32(Qh), sQl = smem_u32(Ql);
    const uint32_t sStg = smem_u32(Stg);

    #pragma unroll
    for (int e = tid; e < 1024; e += 256) {
        const int r = e >> 3, c = (e & 7) * 8;
        *(uint4*)(Qh + r * GPAD + c) = *(const uint4*)(qhg + r * 64 + c);
        *(uint4*)(Ql + r * GPAD + c) = *(const uint4*)(qlg + r * 64 + c);
    }

    const int nkb = qb + 1;

    const int f_r = tid >> 3;
    const int f_c = (tid & 7) * 8;
    auto fill_stage = [&](int stage, int kb) {
        const size_t gofs = (size_t)kb * 128 * DKk;
        const uint32_t sb = sStg + stage * ASTAGE * 2;
        #pragma unroll
        for (int i = 0; i < 4; ++i) {
            const int r = f_r + i * 32;
            const uint32_t so = (r * GPAD + f_c) * 2;
            const size_t go = gofs + r * 64 + f_c;
            CP16(sb + 0 * 128 * GPAD * 2 + so, khg + go);
            CP16(sb + 1 * 128 * GPAD * 2 + so, klg + go);
            CP16(sb + 2 * 128 * GPAD * 2 + so, vhg + go);
            CP16(sb + 3 * 128 * GPAD * 2 + so, vlg + go);
        }
        CP_COMMIT();
    };

    fill_stage(0, 0);
    __syncthreads();

    const int a_row = lane & 15;
    const int a_col = (lane & 16) >> 1;
    const int b_row = (lane & 7) + ((lane & 16) >> 1);
    const int b_col = lane & 8;
    const int v_key = ((lane >> 3) & 1) * 8 + (lane & 7);
    const int v_dim = (lane >> 4) * 8;

    uint32_t qfh[4][4], qfl[4][4];
    #pragma unroll
    for (int kt = 0; kt < 4; ++kt) {
        const uint32_t off = ((wq + a_row) * GPAD + kt * 16 + a_col) * 2;
        ldm_x4(qfh[kt], sQh + off);
        ldm_x4(qfl[kt], sQl + off);
    }

    float O[8][4];
    #pragma unroll
    for (int nf = 0; nf < 8; ++nf)
        #pragma unroll
        for (int j = 0; j < 4; ++j) O[nf][j] = 0.f;
    float mrow[2] = {-INFINITY, -INFINITY};
    float lrow[2] = {0.f, 0.f};

    const int lr = lane >> 2;
    const int lc2 = (lane & 3) * 2;
    const int q0 = qb * 128 + wq + lr;

    for (int kb = 0; kb < nkb; ++kb) {
        const int st = kb & 1;
        CP_WAIT0();
        __syncthreads();

        const uint32_t sKh = sStg + (st * ASTAGE + 0 * 128 * GPAD) * 2;
        const uint32_t sKl = sStg + (st * ASTAGE + 1 * 128 * GPAD) * 2;
        const uint32_t sVh = sStg + (st * ASTAGE + 2 * 128 * GPAD) * 2;
        const uint32_t sVl = sStg + (st * ASTAGE + 3 * 128 * GPAD) * 2;

        // ---- scores = Q K^T (Q pre-scaled into log2 units) ----
        float acc[16][4];
        #pragma unroll
        for (int nf = 0; nf < 16; ++nf)
            #pragma unroll
            for (int j = 0; j < 4; ++j) acc[nf][j] = 0.f;

        {
            uint32_t KHf[2][2][2], KLf[2][2][2];
            auto loadK = [&](int buf, int it2) {
                const int kt2 = it2 >> 3, ntp2 = it2 & 7;
                const uint32_t off =
                    ((ntp2 * 16 + b_row) * GPAD + kt2 * 16 + b_col) * 2;
                uint32_t r4[4];
                ldm_x4(r4, sKh + off);
                KHf[buf][0][0] = r4[0]; KHf[buf][0][1] = r4[1];
                KHf[buf][1][0] = r4[2]; KHf[buf][1][1] = r4[3];
                ldm_x4(r4, sKl + off);
                KLf[buf][0][0] = r4[0]; KLf[buf][0][1] = r4[1];
                KLf[buf][1][0] = r4[2]; KLf[buf][1][1] = r4[3];
            };
            loadK(0, 0);
            #pragma unroll
            for (int it = 0; it < 32; ++it) {
                const int kt = it >> 3, ntp = it & 7, cur = it & 1;
                if (it < 31) loadK(cur ^ 1, it + 1);
                mma_bf16(acc[2*ntp],   qfh[kt], KHf[cur][0]);
                mma_bf16(acc[2*ntp+1], qfh[kt], KHf[cur][1]);
                mma_bf16(acc[2*ntp],   qfh[kt], KLf[cur][0]);
                mma_bf16(acc[2*ntp+1], qfh[kt], KLf[cur][1]);
                mma_bf16(acc[2*ntp],   qfl[kt], KHf[cur][0]);
                mma_bf16(acc[2*ntp+1], qfl[kt], KHf[cur][1]);
            }
        }

        // mid-iteration fill: hidden behind softmax ALU/MUFU work
        if (kb + 1 < nkb) fill_stage(st ^ 1, kb + 1);

        // ---- causal mask ----
        if (kb == qb) {
            #pragma unroll
            for (int nf = 0; nf < 16; ++nf) {
                #pragma unroll
                for (int j = 0; j < 4; ++j) {
                    const int kgl = kb * 128 + nf * 8 + lc2 + (j & 1);
                    const int qgl = q0 + 8 * (j >> 1);
                    if (kgl > qgl) acc[nf][j] = -1e30f;
                }
            }
        }

        // ---- online softmax in log2 units (per row-half) ----
        #pragma unroll
        for (int half = 0; half < 2; ++half) {
            float rm = -1e30f;
            #pragma unroll
            for (int nf = 0; nf < 16; ++nf)
                rm = fmaxf(rm, fmaxf(acc[nf][2*half], acc[nf][2*half+1]));
            rm = fmaxf(rm, __shfl_xor_sync(0xffffffffu, rm, 1));
            rm = fmaxf(rm, __shfl_xor_sync(0xffffffffu, rm, 2));
            const float mn = fmaxf(mrow[half], rm);
            const float alpha = ex2(mrow[half] - mn);
            mrow[half] = mn;
            float rs = 0.f;
            #pragma unroll
            for (int nf = 0; nf < 16; ++nf) {
                const float p0 = ex2(acc[nf][2*half]   - mn);
                const float p1 = ex2(acc[nf][2*half+1] - mn);
                acc[nf][2*half]   = p0;
                acc[nf][2*half+1] = p1;
                rs += p0 + p1;
            }
            rs += __shfl_xor_sync(0xffffffffu, rs, 1);
            rs += __shfl_xor_sync(0xffffffffu, rs, 2);
            lrow[half] = lrow[half] * alpha + rs;
            #pragma unroll
            for (int nf = 0; nf < 8; ++nf) {
                O[nf][2*half]   *= alpha;
                O[nf][2*half+1] *= alpha;
            }
        }

        // ---- O += P V ----
        {
            uint32_t VHf[2][2][2], VLf[2][2][2];
            uint32_t ah[4], al[4];
            auto loadV = [&](int buf, int it2) {
                const int kt2 = it2 >> 2, nd2 = it2 & 3;
                const uint32_t off =
                    ((kt2 * 16 + v_key) * GPAD + nd2 * 16 + v_dim) * 2;
                uint32_t r4[4];
                ldm_x4_t(r4, sVh + off);
                VHf[buf][0][0] = r4[0]; VHf[buf][0][1] = r4[1];
                VHf[buf][1][0] = r4[2]; VHf[buf][1][1] = r4[3];
                ldm_x4_t(r4, sVl + off);
                VLf[buf][0][0] = r4[0]; VLf[buf][0][1] = r4[1];
                VLf[buf][1][0] = r4[2]; VLf[buf][1][1] = r4[3];
            };
            auto packP = [&](int kt) {
                #pragma unroll
                for (int f = 0; f < 4; ++f) {
                    const float p0 = acc[2*kt + (f >> 1)][(f & 1) * 2 + 0];
                    const float p1 = acc[2*kt + (f >> 1)][(f & 1) * 2 + 1];
                    split2_pack(p0, p1, ah[f], al[f]);
                }
            };
            packP(0);
            loadV(0, 0);
            #pragma unroll
            for (int it = 0; it < 32; ++it) {
                const int kt = it >> 2, nd = it & 3, cur = it & 1;
                if (it < 31) loadV(cur ^ 1, it + 1);
                mma_bf16(O[2*nd],   ah, VHf[cur][0]);
                mma_bf16(O[2*nd+1], ah, VHf[cur][1]);
                mma_bf16(O[2*nd],   ah, VLf[cur][0]);
                mma_bf16(O[2*nd+1], ah, VLf[cur][1]);
                mma_bf16(O[2*nd],   al, VHf[cur][0]);
                mma_bf16(O[2*nd+1], al, VHf[cur][1]);
                if (nd == 3 && kt < 7) packP(kt + 1);
            }
        }
    }

    // ---- normalize + split-store ----
    #pragma unroll
    for (int half = 0; half < 2; ++half) {
        const int qgl = q0 + 8 * half;
        const float inv = 1.0f / lrow[half];
        const size_t base = ((size_t)bidx * Ss + qgl) * Dd + head * 64;
        #pragma unroll
        for (int nf = 0; nf < 8; ++nf) {
            const float f0 = O[nf][2*half] * inv;
            const float f1 = O[nf][2*half+1] * inv;
            uint32_t hh, ll;
            split2_pack(f0, f1, hh, ll);
            *(uint32_t*)(g_ath + base + nf * 8 + lc2) = hh;
            *(uint32_t*)(g_atl + base + nf * 8 + lc2) = ll;
        }
    }
}

// ---------------------------------------------------------------------------
extern "C" void kernel_launch(void* const* d_in, const int* in_sizes, int n_in,
                              void* d_out, int out_size)
{
    const float* query = (const float*)d_in[0];
    const float* key   = (const float*)d_in[1];
    const float* value = (const float*)d_in[2];
    const float* Wq = (const float*)d_in[3];
    const float* bq = (const float*)d_in[4];
    const float* Wk = (const float*)d_in[5];
    const float* bk = (const float*)d_in[6];
    const float* Wv = (const float*)d_in[7];
    const float* bv = (const float*)d_in[8];
    const float* Wo = (const float*)d_in[9];
    const float* bo = (const float*)d_in[10];
    float* out = (float*)d_out;

    __nv_bfloat16 *qh, *ql, *kh, *kl, *vh, *vl, *ath, *atl, *wth, *wtl, *ish, *isl;
    cudaGetSymbolAddress((void**)&qh, g_qh);
    cudaGetSymbolAddress((void**)&ql, g_ql);
    cudaGetSymbolAddress((void**)&kh, g_kh);
    cudaGetSymbolAddress((void**)&kl, g_kl);
    cudaGetSymbolAddress((void**)&vh, g_vh);
    cudaGetSymbolAddress((void**)&vl, g_vl);
    cudaGetSymbolAddress((void**)&ath, g_ath);
    cudaGetSymbolAddress((void**)&atl, g_atl);
    cudaGetSymbolAddress((void**)&wth, g_wth);
    cudaGetSymbolAddress((void**)&wtl, g_wtl);
    cudaGetSymbolAddress((void**)&ish, g_insh);
    cudaGetSymbolAddress((void**)&isl, g_insl);

    // Fused prep: weights (z=0..3) + inputs (z=4..6) + rope table (z=7)
    prep_all<<<dim3(32, 32, 8), 256>>>(Wq, Wk, Wv, Wo, query, key, value,
                                       wth, wtl);

    const int gsmem = 2 * GSTAGE * (int)sizeof(__nv_bfloat16);   // 147456
    cudaFuncSetAttribute(gemm_mma<1>, cudaFuncAttributeMaxDynamicSharedMemorySize, gsmem);
    cudaFuncSetAttribute(gemm_mma<0>, cudaFuncAttributeMaxDynamicSharedMemorySize, gsmem);

    // Fused QKV projection: grid.x = 3 weights x 8 n-tiles
    gemm_mma<1><<<dim3(24, 32), 512, gsmem>>>(
        ish, isl, wth, wtl, bq, bk, bv, nullptr,
        qh, ql, kh, kl, vh, vl);

    const int asmem = (2 * 128 * GPAD + 2 * ASTAGE) *
                      (int)sizeof(__nv_bfloat16);   // 184320
    cudaFuncSetAttribute(attn_mma, cudaFuncAttributeMaxDynamicSharedMemorySize, asmem);
    attn_mma<<<dim3(Ss / 128, Bb * Hh), 256, asmem>>>();

    // Output projection (fp32 out)
    gemm_mma<0><<<dim3(8, 32), 512, gsmem>>>(
        ath, atl, wth + 3u * 1048576, wtl + 3u * 1048576, bo, nullptr, nullptr,
        out, nullptr, nullptr, nullptr, nullptr, nullptr, nullptr);
}